// round 8
// baseline (speedup 1.0000x reference)
#include <cuda_runtime.h>
#include <cuda_bf16.h>
#include <mma.h>
#include <cstdint>

using namespace nvcuda;
typedef __nv_bfloat16 bft;

constexpr int Bq = 16, Cc = 512, Nn = 4096;

// Scratch (device globals — no allocation allowed)
__device__ __align__(16) bft g_embh[2][Bq][Cc][Nn];   // bf16 rgb/geo
__device__ __align__(16) bft g_qkv[6][Bq][Cc][Nn];    // 0:Qp2r 1:Kp2r 2:Vp2r 3:Qr2p 4:Kr2p 5:Vr2p
__device__ __align__(16) bft g_wbf[8][Cc][Cc];        // 0..5 qkv weights, 6:proj_p2r 7:proj_r2p
__device__ __align__(16) bft g_outb[2][Bq][Cc][Nn];   // attention outputs per branch
__device__ __align__(16) float g_part[2][Bq][8][4][64][64];  // partial logits (4 N-splits)
__device__ __align__(16) bft g_probs[2][Bq][8][64][64];      // softmaxed probs

// ---------------------------------------------------------------------------
// cp.async helpers
// ---------------------------------------------------------------------------
__device__ __forceinline__ void cp16(void* s, const void* g) {
    unsigned ss = (unsigned)__cvta_generic_to_shared(s);
    asm volatile("cp.async.cg.shared.global [%0], [%1], 16;\n" ::"r"(ss), "l"(g));
}
__device__ __forceinline__ void cpcommit() { asm volatile("cp.async.commit_group;\n"); }
template <int W>
__device__ __forceinline__ void cpwait() { asm volatile("cp.async.wait_group %0;\n" ::"n"(W)); }

// ---------------------------------------------------------------------------
// K1a: convert embeddings fp32 -> bf16
// ---------------------------------------------------------------------------
__global__ void k_convert(const float* __restrict__ rgb, const float* __restrict__ geo) {
    size_t i = (size_t)(blockIdx.x * blockDim.x + threadIdx.x) * 4;
    float4 a = *reinterpret_cast<const float4*>(rgb + i);
    float4 b = *reinterpret_cast<const float4*>(geo + i);
    __nv_bfloat162* pr = reinterpret_cast<__nv_bfloat162*>(&g_embh[0][0][0][0] + i);
    __nv_bfloat162* pg = reinterpret_cast<__nv_bfloat162*>(&g_embh[1][0][0][0] + i);
    pr[0] = __floats2bfloat162_rn(a.x, a.y);
    pr[1] = __floats2bfloat162_rn(a.z, a.w);
    pg[0] = __floats2bfloat162_rn(b.x, b.y);
    pg[1] = __floats2bfloat162_rn(b.z, b.w);
}

// K1b: convert 8 weight matrices fp32 -> bf16
__global__ void k_convw(const float* w0, const float* w1, const float* w2, const float* w3,
                        const float* w4, const float* w5, const float* w6, const float* w7) {
    const float* ws[8] = {w0, w1, w2, w3, w4, w5, w6, w7};
    const int s = blockIdx.y;
    size_t i = (size_t)(blockIdx.x * blockDim.x + threadIdx.x) * 4;
    float4 a = *reinterpret_cast<const float4*>(ws[s] + i);
    __nv_bfloat162* p = reinterpret_cast<__nv_bfloat162*>(&g_wbf[s][0][0] + i);
    p[0] = __floats2bfloat162_rn(a.x, a.y);
    p[1] = __floats2bfloat162_rn(a.z, a.w);
}

// ---------------------------------------------------------------------------
// K2: QKV projections. C[512,4096] = W[512,512] @ X[512,4096].
// Tile 128(M) x 256(N), BK=64, 3-stage cp.async, 512 threads (16 warps 2x8,
// warp tile 64x32, acc 4x2). smem: As[3][128][72] (55296) | Bs[3][64][264]
// (101376) = 156672. grid=(16,4,96 = bb*6+combo)
// ---------------------------------------------------------------------------
__global__ __launch_bounds__(512) void k_gemm_qkv() {
    extern __shared__ char sm[];
    bft (*As)[128][72] = reinterpret_cast<bft (*)[128][72]>(sm);
    bft (*Bs)[64][264] = reinterpret_cast<bft (*)[64][264]>(sm + 55296);

    const int z = blockIdx.z;
    const int bb = z / 6, combo = z % 6;
    const int geo_src = (combo >= 1 && combo <= 3) ? 1 : 0;
    const bft* __restrict__ Ag = &g_wbf[combo][0][0];
    const bft* __restrict__ Bg = &g_embh[geo_src][bb][0][0];
    bft* __restrict__ Cg = &g_qkv[combo][bb][0][0];
    const int m0 = blockIdx.y * 128, n0 = blockIdx.x * 256;
    const int tid = threadIdx.x, wid = tid >> 5, lane = tid & 31;
    const int wm = (wid & 1) * 64, wn = (wid >> 1) * 32;

    wmma::fragment<wmma::accumulator, 16, 16, 16, float> acc[4][2];
#pragma unroll
    for (int i = 0; i < 4; i++)
#pragma unroll
        for (int j = 0; j < 2; j++) wmma::fill_fragment(acc[i][j], 0.0f);

    auto pre = [&](int it, int buf) {
        const int k0 = it * 64;
#pragma unroll
        for (int p = 0; p < 2; p++) {
            int idx = tid + p * 512;
            int r = idx >> 3, c = (idx & 7) * 8;
            cp16(&As[buf][r][c], Ag + (m0 + r) * 512 + k0 + c);
        }
#pragma unroll
        for (int p = 0; p < 4; p++) {
            int idx = tid + p * 512;
            int r = idx >> 5, c = (idx & 31) * 8;
            cp16(&Bs[buf][r][c], Bg + (size_t)(k0 + r) * 4096 + n0 + c);
        }
        cpcommit();
    };

    pre(0, 0);
    pre(1, 1);
    for (int it = 0; it < 8; ++it) {
        const int buf = it % 3;
        if (it < 7) cpwait<1>();
        else        cpwait<0>();
        __syncthreads();
        if (it + 2 < 8) pre(it + 2, (it + 2) % 3);
#pragma unroll
        for (int kk = 0; kk < 64; kk += 16) {
            wmma::fragment<wmma::matrix_a, 16, 16, 16, bft, wmma::row_major> af[4];
            wmma::fragment<wmma::matrix_b, 16, 16, 16, bft, wmma::row_major> bfr[2];
#pragma unroll
            for (int i = 0; i < 4; i++)
                wmma::load_matrix_sync(af[i], &As[buf][wm + i * 16][kk], 72);
#pragma unroll
            for (int j = 0; j < 2; j++)
                wmma::load_matrix_sync(bfr[j], &Bs[buf][kk][wn + j * 16], 264);
#pragma unroll
            for (int i = 0; i < 4; i++)
#pragma unroll
                for (int j = 0; j < 2; j++)
                    wmma::mma_sync(acc[i][j], af[i], bfr[j], acc[i][j]);
        }
    }
    __syncthreads();

    // Epilogue: per-warp 16x32 fp32 staging -> bf16
    float* Cw = reinterpret_cast<float*>(sm) + wid * 512;
#pragma unroll
    for (int i = 0; i < 4; i++) {
        wmma::store_matrix_sync(Cw, acc[i][0], 32, wmma::mem_row_major);
        wmma::store_matrix_sync(Cw + 16, acc[i][1], 32, wmma::mem_row_major);
        __syncwarp();
        const int r = lane & 15, half = lane >> 4;
        const float* src = Cw + r * 32 + half * 16;
        bft* dst = Cg + (size_t)(m0 + wm + i * 16 + r) * 4096 + n0 + wn + half * 16;
        uint4 o[2];
        __nv_bfloat162* ph = reinterpret_cast<__nv_bfloat162*>(o);
#pragma unroll
        for (int q = 0; q < 8; q++) ph[q] = __floats2bfloat162_rn(src[2 * q], src[2 * q + 1]);
        reinterpret_cast<uint4*>(dst)[0] = o[0];
        reinterpret_cast<uint4*>(dst)[1] = o[1];
        __syncwarp();
    }
}

// ---------------------------------------------------------------------------
// K4: fused output projections + residual (same layout as K2, 16 chunks).
// grid=(16,4,16), 512 thr, dyn smem 156672
// ---------------------------------------------------------------------------
__global__ __launch_bounds__(512) void k_gemm_final(const float* __restrict__ rgb,
                                                    const float* __restrict__ geo,
                                                    float* __restrict__ out) {
    extern __shared__ char sm[];
    bft (*As)[128][72] = reinterpret_cast<bft (*)[128][72]>(sm);
    bft (*Bs)[64][264] = reinterpret_cast<bft (*)[64][264]>(sm + 55296);

    const int bb = blockIdx.z;
    const int m0 = blockIdx.y * 128, n0 = blockIdx.x * 256;
    const int tid = threadIdx.x, wid = tid >> 5, lane = tid & 31;
    const int wm = (wid & 1) * 64, wn = (wid >> 1) * 32;

    wmma::fragment<wmma::accumulator, 16, 16, 16, float> acc[4][2];
#pragma unroll
    for (int i = 0; i < 4; i++)
#pragma unroll
        for (int j = 0; j < 2; j++) wmma::fill_fragment(acc[i][j], 0.0f);

    auto pre = [&](int ck, int buf) {
        const int brn = ck >> 3, k0 = (ck & 7) * 64;
        const bft* Ag = &g_wbf[6 + brn][0][0];
        const bft* Bg = &g_outb[brn][bb][0][0];
#pragma unroll
        for (int p = 0; p < 2; p++) {
            int idx = tid + p * 512;
            int r = idx >> 3, c = (idx & 7) * 8;
            cp16(&As[buf][r][c], Ag + (m0 + r) * 512 + k0 + c);
        }
#pragma unroll
        for (int p = 0; p < 4; p++) {
            int idx = tid + p * 512;
            int r = idx >> 5, c = (idx & 31) * 8;
            cp16(&Bs[buf][r][c], Bg + (size_t)(k0 + r) * 4096 + n0 + c);
        }
        cpcommit();
    };

    pre(0, 0);
    pre(1, 1);
    for (int it = 0; it < 16; ++it) {
        const int buf = it % 3;
        if (it < 15) cpwait<1>();
        else         cpwait<0>();
        __syncthreads();
        if (it + 2 < 16) pre(it + 2, (it + 2) % 3);
#pragma unroll
        for (int kk = 0; kk < 64; kk += 16) {
            wmma::fragment<wmma::matrix_a, 16, 16, 16, bft, wmma::row_major> af[4];
            wmma::fragment<wmma::matrix_b, 16, 16, 16, bft, wmma::row_major> bfr[2];
#pragma unroll
            for (int i = 0; i < 4; i++)
                wmma::load_matrix_sync(af[i], &As[buf][wm + i * 16][kk], 72);
#pragma unroll
            for (int j = 0; j < 2; j++)
                wmma::load_matrix_sync(bfr[j], &Bs[buf][kk][wn + j * 16], 264);
#pragma unroll
            for (int i = 0; i < 4; i++)
#pragma unroll
                for (int j = 0; j < 2; j++)
                    wmma::mma_sync(acc[i][j], af[i], bfr[j], acc[i][j]);
        }
    }
    __syncthreads();

    // Epilogue: out = acc + rgb + geo (fp32)
    float* Cw = reinterpret_cast<float*>(sm) + wid * 512;
    const size_t bplane = (size_t)bb * Cc * Nn;
#pragma unroll
    for (int i = 0; i < 4; i++) {
        wmma::store_matrix_sync(Cw, acc[i][0], 32, wmma::mem_row_major);
        wmma::store_matrix_sync(Cw + 16, acc[i][1], 32, wmma::mem_row_major);
        __syncwarp();
        const int r = lane & 15, half = lane >> 4;
        const float* src = Cw + r * 32 + half * 16;
        const size_t off = bplane + (size_t)(m0 + wm + i * 16 + r) * 4096 + n0 + wn + half * 16;
#pragma unroll
        for (int q = 0; q < 4; q++) {
            float4 a = reinterpret_cast<const float4*>(src)[q];
            float4 rr = reinterpret_cast<const float4*>(rgb + off)[q];
            float4 gg = reinterpret_cast<const float4*>(geo + off)[q];
            a.x += rr.x + gg.x;
            a.y += rr.y + gg.y;
            a.z += rr.z + gg.z;
            a.w += rr.w + gg.w;
            reinterpret_cast<float4*>(out + off)[q] = a;
        }
        __syncwarp();
    }
}

// ---------------------------------------------------------------------------
// K3a: partial logits. L_part[64,64] = Q[64, ns-range] . K^T over 1024 cols.
// grid=(4 ns, 8 h, 32 = br*16+bb), 256 thr.
// dyn smem 102400: QS[2][64][136] @0, KS[2][64][136] @34816, Ls[2][64][64] @69632
// ---------------------------------------------------------------------------
__global__ __launch_bounds__(256) void k_attn1() {
    extern __shared__ char sm[];
    bft (*QS)[64][136] = reinterpret_cast<bft (*)[64][136]>(sm);
    bft (*KS)[64][136] = reinterpret_cast<bft (*)[64][136]>(sm + 34816);
    float (*Ls)[64][64] = reinterpret_cast<float (*)[64][64]>(sm + 69632);

    const int ns = blockIdx.x, h = blockIdx.y, z = blockIdx.z;
    const int br = z >> 4, bb = z & 15;
    const bft* __restrict__ Q  = &g_qkv[br * 3 + 0][bb][h * 64][0] + ns * 1024;
    const bft* __restrict__ Kk = &g_qkv[br * 3 + 1][bb][h * 64][0] + ns * 1024;
    const int tid = threadIdx.x, wid = tid >> 5;
    const int wm = (wid & 3) * 16, kh = wid >> 2;

    wmma::fragment<wmma::accumulator, 16, 16, 16, float> acc[4];
#pragma unroll
    for (int j = 0; j < 4; j++) wmma::fill_fragment(acc[j], 0.0f);

    auto pre = [&](int c, int buf) {
#pragma unroll
        for (int p = 0; p < 4; p++) {
            int idx = tid + p * 256;
            int r = idx >> 4, cl = (idx & 15) * 8;
            cp16(&QS[buf][r][cl], Q + (size_t)r * 4096 + c * 128 + cl);
            cp16(&KS[buf][r][cl], Kk + (size_t)r * 4096 + c * 128 + cl);
        }
        cpcommit();
    };
    pre(0, 0);
    for (int c = 0; c < 8; ++c) {
        const int buf = c & 1;
        cpwait<0>();
        __syncthreads();
        if (c < 7) pre(c + 1, buf ^ 1);
#pragma unroll
        for (int ks = 0; ks < 4; ks++) {
            wmma::fragment<wmma::matrix_a, 16, 16, 16, bft, wmma::row_major> af;
            wmma::load_matrix_sync(af, &QS[buf][wm][kh * 64 + ks * 16], 136);
#pragma unroll
            for (int j = 0; j < 4; j++) {
                wmma::fragment<wmma::matrix_b, 16, 16, 16, bft, wmma::col_major> bfr;
                wmma::load_matrix_sync(bfr, &KS[buf][j * 16][kh * 64 + ks * 16], 136);
                wmma::mma_sync(acc[j], af, bfr, acc[j]);
            }
        }
    }
#pragma unroll
    for (int j = 0; j < 4; j++)
        wmma::store_matrix_sync(&Ls[kh][wm][j * 16], acc[j], 64, wmma::mem_row_major);
    __syncthreads();

    // partial write: 256 threads x 16 floats
    {
        const int r = tid >> 2, c0 = (tid & 3) * 16;
        float* dst = &g_part[br][bb][h][ns][r][c0];
#pragma unroll
        for (int j = 0; j < 4; j++) {
            float4 a = *reinterpret_cast<const float4*>(&Ls[0][r][c0 + j * 4]);
            float4 b = *reinterpret_cast<const float4*>(&Ls[1][r][c0 + j * 4]);
            a.x += b.x; a.y += b.y; a.z += b.z; a.w += b.w;
            reinterpret_cast<float4*>(dst)[j] = a;
        }
    }
}

// ---------------------------------------------------------------------------
// K3b: reduce partials + softmax -> bf16 probs. grid=(8 h, 32 z), 64 thr.
// ---------------------------------------------------------------------------
__global__ __launch_bounds__(64) void k_softmax() {
    const int h = blockIdx.x, z = blockIdx.y;
    const int br = z >> 4, bb = z & 15;
    const int r = threadIdx.x;
    const float* p0 = &g_part[br][bb][h][0][r][0];
    float v[64];
#pragma unroll
    for (int j = 0; j < 16; j++) {
        float4 a = reinterpret_cast<const float4*>(p0)[j];
#pragma unroll
        for (int s = 1; s < 4; s++) {
            float4 b = reinterpret_cast<const float4*>(p0 + s * 4096)[j];
            a.x += b.x; a.y += b.y; a.z += b.z; a.w += b.w;
        }
        v[j * 4 + 0] = a.x; v[j * 4 + 1] = a.y; v[j * 4 + 2] = a.z; v[j * 4 + 3] = a.w;
    }
    const float scale = 0.125f;
    float mx = -1e30f;
#pragma unroll
    for (int j = 0; j < 64; j++) { v[j] *= scale; mx = fmaxf(mx, v[j]); }
    float s = 0.f;
#pragma unroll
    for (int j = 0; j < 64; j++) { v[j] = __expf(v[j] - mx); s += v[j]; }
    float inv = 1.0f / s;
    uint4 o[8];  // 64 bf16 = 128 bytes  (R7 bug: was o[4] -> overflow + half-row write)
    __nv_bfloat162* ph = reinterpret_cast<__nv_bfloat162*>(o);
#pragma unroll
    for (int j = 0; j < 32; j++) ph[j] = __floats2bfloat162_rn(v[2 * j] * inv, v[2 * j + 1] * inv);
    uint4* dst = reinterpret_cast<uint4*>(&g_probs[br][bb][h][r][0]);
#pragma unroll
    for (int j = 0; j < 8; j++) dst[j] = o[j];
}

// ---------------------------------------------------------------------------
// K3c: OutT[64, chunk] = probs^T @ V[64, chunk], chunk = 512 cols.
// grid=(8 nc, 8 h, 32 z), 256 thr.
// dyn smem 76800: VS[2][64][136] @0, Ps[64][72] @34816, OSw @44032 (32KB)
// ---------------------------------------------------------------------------
__global__ __launch_bounds__(256) void k_attn2() {
    extern __shared__ char sm[];
    bft (*VS)[64][136] = reinterpret_cast<bft (*)[64][136]>(sm);
    bft (*Ps)[72] = reinterpret_cast<bft (*)[72]>(sm + 34816);

    const int nc = blockIdx.x, h = blockIdx.y, z = blockIdx.z;
    const int br = z >> 4, bb = z & 15;
    const bft* __restrict__ V = &g_qkv[br * 3 + 2][bb][h * 64][0] + nc * 512;
    bft* __restrict__ O = &g_outb[br][bb][h * 64][0] + nc * 512;
    const bft* __restrict__ gp = &g_probs[br][bb][h][0][0];
    const int tid = threadIdx.x, wid = tid >> 5, lane = tid & 31;
    const int we = (wid & 3), wn = (wid >> 2) * 64;

    // load probs into padded smem
#pragma unroll
    for (int p = 0; p < 2; p++) {
        int idx = tid + p * 256;
        int r = idx >> 3, c = (idx & 7) * 8;
        *reinterpret_cast<uint4*>(&Ps[r][c]) =
            *reinterpret_cast<const uint4*>(gp + r * 64 + c);
    }

    auto pre = [&](int c, int buf) {
#pragma unroll
        for (int p = 0; p < 4; p++) {
            int idx = tid + p * 256;
            int r = idx >> 4, cl = (idx & 15) * 8;
            cp16(&VS[buf][r][cl], V + (size_t)r * 4096 + c * 128 + cl);
        }
        cpcommit();
    };
    pre(0, 0);
    __syncthreads();

    wmma::fragment<wmma::matrix_a, 16, 16, 16, bft, wmma::col_major> af[4];
#pragma unroll
    for (int d = 0; d < 4; d++)
        wmma::load_matrix_sync(af[d], &Ps[d * 16][we * 16], 72);

    float* OSw = reinterpret_cast<float*>(sm + 44032) + wid * 1024;  // 16x64 per warp
    for (int c = 0; c < 4; ++c) {
        const int buf = c & 1;
        cpwait<0>();
        __syncthreads();
        if (c < 3) pre(c + 1, buf ^ 1);
#pragma unroll
        for (int n4 = 0; n4 < 4; n4++) {
            wmma::fragment<wmma::accumulator, 16, 16, 16, float> oa;
            wmma::fill_fragment(oa, 0.0f);
#pragma unroll
            for (int d = 0; d < 4; d++) {
                wmma::fragment<wmma::matrix_b, 16, 16, 16, bft, wmma::row_major> bfr;
                wmma::load_matrix_sync(bfr, &VS[buf][d * 16][wn + n4 * 16], 136);
                wmma::mma_sync(oa, af[d], bfr, oa);
            }
            wmma::store_matrix_sync(OSw + n4 * 16, oa, 64, wmma::mem_row_major);
        }
        __syncwarp();
        {
            const int r = lane >> 1, c0 = (lane & 1) * 32;
            const float* src = OSw + r * 64 + c0;
            bft* dst = O + (size_t)(we * 16 + r) * 4096 + c * 128 + wn + c0;
            uint4 o[4];
            __nv_bfloat162* ph = reinterpret_cast<__nv_bfloat162*>(o);
#pragma unroll
            for (int q = 0; q < 16; q++)
                ph[q] = __floats2bfloat162_rn(src[2 * q], src[2 * q + 1]);
#pragma unroll
            for (int q = 0; q < 4; q++) reinterpret_cast<uint4*>(dst)[q] = o[q];
        }
        __syncwarp();
    }
}

// ---------------------------------------------------------------------------
// Launch. Input order: 0 rgb_emb, 1 geo_emb, 2 wq_rgb, 3 wk_rgb, 4 wv_rgb,
// 5 wq_point, 6 wk_point, 7 wv_point, 8 proj_r2p, 9 proj_p2r.
// ---------------------------------------------------------------------------
extern "C" void kernel_launch(void* const* d_in, const int* in_sizes, int n_in,
                              void* d_out, int out_size) {
    const float* rgb = (const float*)d_in[0];
    const float* geo = (const float*)d_in[1];

    cudaFuncSetAttribute(k_gemm_qkv, cudaFuncAttributeMaxDynamicSharedMemorySize, 156672);
    cudaFuncSetAttribute(k_gemm_final, cudaFuncAttributeMaxDynamicSharedMemorySize, 156672);
    cudaFuncSetAttribute(k_attn1, cudaFuncAttributeMaxDynamicSharedMemorySize, 102400);
    cudaFuncSetAttribute(k_attn2, cudaFuncAttributeMaxDynamicSharedMemorySize, 76800);

    k_convert<<<32768, 256>>>(rgb, geo);
    // weight slot order: 0 wq_rgb, 1 wk_point, 2 wv_point, 3 wq_point, 4 wk_rgb,
    //                    5 wv_rgb, 6 proj_p2r, 7 proj_r2p
    k_convw<<<dim3(256, 8), 256>>>((const float*)d_in[2], (const float*)d_in[6],
                                   (const float*)d_in[7], (const float*)d_in[5],
                                   (const float*)d_in[3], (const float*)d_in[4],
                                   (const float*)d_in[9], (const float*)d_in[8]);

    // QKV projections: z = bb*6 + combo (batch-major for L2 reuse)
    k_gemm_qkv<<<dim3(16, 4, 96), 512, 156672>>>();

    // attention: partial logits -> softmax -> probs^T @ V
    k_attn1<<<dim3(4, 8, 32), 256, 102400>>>();
    k_softmax<<<dim3(8, 32), 64>>>();
    k_attn2<<<dim3(8, 8, 32), 256, 76800>>>();

    // fused output projections + residual -> d_out
    k_gemm_final<<<dim3(16, 4, 16), 512, 156672>>>(rgb, geo, (float*)d_out);
}

// round 9
// speedup vs baseline: 1.1082x; 1.1082x over previous
#include <cuda_runtime.h>
#include <cuda_bf16.h>
#include <mma.h>
#include <cstdint>

using namespace nvcuda;
typedef __nv_bfloat16 bft;

constexpr int Bq = 16, Cc = 512, Nn = 4096;

// Scratch (device globals — no allocation allowed)
__device__ __align__(16) bft g_embh[2][Bq][Cc][Nn];   // bf16 rgb/geo
__device__ __align__(16) bft g_qkv[6][Bq][Cc][Nn];    // 0:Qp2r 1:Kp2r 2:Vp2r 3:Qr2p 4:Kr2p 5:Vr2p
__device__ __align__(16) bft g_wbf[8][Cc][Cc];        // 0..5 qkv weights, 6:proj_p2r 7:proj_r2p
__device__ __align__(16) bft g_outb[2][Bq][Cc][Nn];   // attention outputs per branch
__device__ __align__(16) float g_part[2][Bq][8][4][64][64];  // partial logits (4 N-splits)
__device__ __align__(16) bft g_probs[2][Bq][8][64][64];      // softmaxed probs

// ---------------------------------------------------------------------------
// cp.async helpers
// ---------------------------------------------------------------------------
__device__ __forceinline__ void cp16(void* s, const void* g) {
    unsigned ss = (unsigned)__cvta_generic_to_shared(s);
    asm volatile("cp.async.cg.shared.global [%0], [%1], 16;\n" ::"r"(ss), "l"(g));
}
__device__ __forceinline__ void cpcommit() { asm volatile("cp.async.commit_group;\n"); }
template <int W>
__device__ __forceinline__ void cpwait() { asm volatile("cp.async.wait_group %0;\n" ::"n"(W)); }

// ---------------------------------------------------------------------------
// K1a: convert embeddings fp32 -> bf16
// ---------------------------------------------------------------------------
__global__ void k_convert(const float* __restrict__ rgb, const float* __restrict__ geo) {
    size_t i = (size_t)(blockIdx.x * blockDim.x + threadIdx.x) * 4;
    float4 a = *reinterpret_cast<const float4*>(rgb + i);
    float4 b = *reinterpret_cast<const float4*>(geo + i);
    __nv_bfloat162* pr = reinterpret_cast<__nv_bfloat162*>(&g_embh[0][0][0][0] + i);
    __nv_bfloat162* pg = reinterpret_cast<__nv_bfloat162*>(&g_embh[1][0][0][0] + i);
    pr[0] = __floats2bfloat162_rn(a.x, a.y);
    pr[1] = __floats2bfloat162_rn(a.z, a.w);
    pg[0] = __floats2bfloat162_rn(b.x, b.y);
    pg[1] = __floats2bfloat162_rn(b.z, b.w);
}

// K1b: convert 8 weight matrices fp32 -> bf16
__global__ void k_convw(const float* w0, const float* w1, const float* w2, const float* w3,
                        const float* w4, const float* w5, const float* w6, const float* w7) {
    const float* ws[8] = {w0, w1, w2, w3, w4, w5, w6, w7};
    const int s = blockIdx.y;
    size_t i = (size_t)(blockIdx.x * blockDim.x + threadIdx.x) * 4;
    float4 a = *reinterpret_cast<const float4*>(ws[s] + i);
    __nv_bfloat162* p = reinterpret_cast<__nv_bfloat162*>(&g_wbf[s][0][0] + i);
    p[0] = __floats2bfloat162_rn(a.x, a.y);
    p[1] = __floats2bfloat162_rn(a.z, a.w);
}

// Dummy no-op kernel: positions k_gemm_qkv as the 4th launch for ncu capture.
__global__ void k_dummy() {}

// ---------------------------------------------------------------------------
// K2: QKV projections. C[512,4096] = W[512,512] @ X[512,4096].
// Tile 128(M) x 256(N), BK=64, 3-stage cp.async, single barrier per chunk.
// 8 warps as 2(M) x 4(N): warp tile 64x64 (acc 4x4 fp32).
// smem: As[3][128][72] @0 (55296) | Bs[3][64][264] @55296 (101376) = 156672
// grid=(16 n-tiles, 4 m-tiles, 96 = bb*6+combo), 256 thr
// ---------------------------------------------------------------------------
__global__ __launch_bounds__(256) void k_gemm_qkv() {
    extern __shared__ char sm[];
    bft (*As)[128][72] = reinterpret_cast<bft (*)[128][72]>(sm);
    bft (*Bs)[64][264] = reinterpret_cast<bft (*)[64][264]>(sm + 55296);

    const int z = blockIdx.z;
    const int bb = z / 6, combo = z % 6;
    const int geo_src = (combo >= 1 && combo <= 3) ? 1 : 0;
    const bft* __restrict__ Ag = &g_wbf[combo][0][0];
    const bft* __restrict__ Bg = &g_embh[geo_src][bb][0][0];
    bft* __restrict__ Cg = &g_qkv[combo][bb][0][0];
    const int m0 = blockIdx.y * 128, n0 = blockIdx.x * 256;
    const int tid = threadIdx.x, wid = tid >> 5, lane = tid & 31;
    const int wm = (wid & 1) * 64, wn = (wid >> 1) * 64;

    wmma::fragment<wmma::accumulator, 16, 16, 16, float> acc[4][4];
#pragma unroll
    for (int i = 0; i < 4; i++)
#pragma unroll
        for (int j = 0; j < 4; j++) wmma::fill_fragment(acc[i][j], 0.0f);

    auto pre = [&](int it, int buf) {
        const int k0 = it * 64;
#pragma unroll
        for (int p = 0; p < 4; p++) {
            int idx = tid + p * 256;
            int r = idx >> 3, c = (idx & 7) * 8;
            cp16(&As[buf][r][c], Ag + (m0 + r) * 512 + k0 + c);
        }
#pragma unroll
        for (int p = 0; p < 8; p++) {
            int idx = tid + p * 256;
            int r = idx >> 5, c = (idx & 31) * 8;
            cp16(&Bs[buf][r][c], Bg + (size_t)(k0 + r) * 4096 + n0 + c);
        }
        cpcommit();
    };

    pre(0, 0);
    pre(1, 1);
    for (int it = 0; it < 8; ++it) {
        const int buf = it % 3;
        if (it < 7) cpwait<1>();
        else        cpwait<0>();
        __syncthreads();
        if (it + 2 < 8) pre(it + 2, (it + 2) % 3);
#pragma unroll
        for (int kk = 0; kk < 64; kk += 16) {
            wmma::fragment<wmma::matrix_a, 16, 16, 16, bft, wmma::row_major> af[4];
#pragma unroll
            for (int i = 0; i < 4; i++)
                wmma::load_matrix_sync(af[i], &As[buf][wm + i * 16][kk], 72);
#pragma unroll
            for (int j = 0; j < 4; j++) {
                wmma::fragment<wmma::matrix_b, 16, 16, 16, bft, wmma::row_major> bfr;
                wmma::load_matrix_sync(bfr, &Bs[buf][kk][wn + j * 16], 264);
#pragma unroll
                for (int i = 0; i < 4; i++)
                    wmma::mma_sync(acc[i][j], af[i], bfr, acc[i][j]);
            }
        }
    }
    __syncthreads();

    // Epilogue: per-warp 16x64 fp32 staging (aliases tile smem), fp32 -> bf16.
    float* Cw = reinterpret_cast<float*>(sm) + wid * 1024;
#pragma unroll
    for (int i = 0; i < 4; i++) {
#pragma unroll
        for (int j = 0; j < 4; j++)
            wmma::store_matrix_sync(Cw + j * 16, acc[i][j], 64, wmma::mem_row_major);
        __syncwarp();
        const int r = lane >> 1, c0 = (lane & 1) * 32;
        const float* src = Cw + r * 64 + c0;
        bft* dst = Cg + (size_t)(m0 + wm + i * 16 + r) * 4096 + n0 + wn + c0;
        uint4 o[4];
        __nv_bfloat162* ph = reinterpret_cast<__nv_bfloat162*>(o);
#pragma unroll
        for (int q = 0; q < 16; q++) ph[q] = __floats2bfloat162_rn(src[2 * q], src[2 * q + 1]);
#pragma unroll
        for (int q = 0; q < 4; q++) reinterpret_cast<uint4*>(dst)[q] = o[q];
        __syncwarp();
    }
}

// ---------------------------------------------------------------------------
// K4: fused output projections + residual:
//   out[b] = proj_p2r @ Out0 + proj_r2p @ Out1 + rgb + geo
// Same tiling as K2; 16 chunks (2 branches x 8 k-steps of 64).
// grid=(16,4,16), 256 thr, dyn smem 156672
// ---------------------------------------------------------------------------
__global__ __launch_bounds__(256) void k_gemm_final(const float* __restrict__ rgb,
                                                    const float* __restrict__ geo,
                                                    float* __restrict__ out) {
    extern __shared__ char sm[];
    bft (*As)[128][72] = reinterpret_cast<bft (*)[128][72]>(sm);
    bft (*Bs)[64][264] = reinterpret_cast<bft (*)[64][264]>(sm + 55296);

    const int bb = blockIdx.z;
    const int m0 = blockIdx.y * 128, n0 = blockIdx.x * 256;
    const int tid = threadIdx.x, wid = tid >> 5, lane = tid & 31;
    const int wm = (wid & 1) * 64, wn = (wid >> 1) * 64;

    wmma::fragment<wmma::accumulator, 16, 16, 16, float> acc[4][4];
#pragma unroll
    for (int i = 0; i < 4; i++)
#pragma unroll
        for (int j = 0; j < 4; j++) wmma::fill_fragment(acc[i][j], 0.0f);

    auto pre = [&](int ck, int buf) {
        const int brn = ck >> 3, k0 = (ck & 7) * 64;
        const bft* Ag = &g_wbf[6 + brn][0][0];
        const bft* Bg = &g_outb[brn][bb][0][0];
#pragma unroll
        for (int p = 0; p < 4; p++) {
            int idx = tid + p * 256;
            int r = idx >> 3, c = (idx & 7) * 8;
            cp16(&As[buf][r][c], Ag + (m0 + r) * 512 + k0 + c);
        }
#pragma unroll
        for (int p = 0; p < 8; p++) {
            int idx = tid + p * 256;
            int r = idx >> 5, c = (idx & 31) * 8;
            cp16(&Bs[buf][r][c], Bg + (size_t)(k0 + r) * 4096 + n0 + c);
        }
        cpcommit();
    };

    pre(0, 0);
    pre(1, 1);
    for (int it = 0; it < 16; ++it) {
        const int buf = it % 3;
        if (it < 15) cpwait<1>();
        else         cpwait<0>();
        __syncthreads();
        if (it + 2 < 16) pre(it + 2, (it + 2) % 3);
#pragma unroll
        for (int kk = 0; kk < 64; kk += 16) {
            wmma::fragment<wmma::matrix_a, 16, 16, 16, bft, wmma::row_major> af[4];
#pragma unroll
            for (int i = 0; i < 4; i++)
                wmma::load_matrix_sync(af[i], &As[buf][wm + i * 16][kk], 72);
#pragma unroll
            for (int j = 0; j < 4; j++) {
                wmma::fragment<wmma::matrix_b, 16, 16, 16, bft, wmma::row_major> bfr;
                wmma::load_matrix_sync(bfr, &Bs[buf][kk][wn + j * 16], 264);
#pragma unroll
                for (int i = 0; i < 4; i++)
                    wmma::mma_sync(acc[i][j], af[i], bfr, acc[i][j]);
            }
        }
    }
    __syncthreads();

    // Epilogue: out = acc + rgb + geo (fp32)
    float* Cw = reinterpret_cast<float*>(sm) + wid * 1024;
    const size_t bplane = (size_t)bb * Cc * Nn;
#pragma unroll
    for (int i = 0; i < 4; i++) {
#pragma unroll
        for (int j = 0; j < 4; j++)
            wmma::store_matrix_sync(Cw + j * 16, acc[i][j], 64, wmma::mem_row_major);
        __syncwarp();
        const int r = lane >> 1, c0 = (lane & 1) * 32;
        const float* src = Cw + r * 64 + c0;
        const size_t off = bplane + (size_t)(m0 + wm + i * 16 + r) * 4096 + n0 + wn + c0;
#pragma unroll
        for (int q = 0; q < 8; q++) {
            float4 a = reinterpret_cast<const float4*>(src)[q];
            float4 rr = reinterpret_cast<const float4*>(rgb + off)[q];
            float4 gg = reinterpret_cast<const float4*>(geo + off)[q];
            a.x += rr.x + gg.x;
            a.y += rr.y + gg.y;
            a.z += rr.z + gg.z;
            a.w += rr.w + gg.w;
            reinterpret_cast<float4*>(out + off)[q] = a;
        }
        __syncwarp();
    }
}

// ---------------------------------------------------------------------------
// K3a: partial logits. L_part[64,64] = Q[64, ns-range] . K^T over 1024 cols.
// grid=(4 ns, 8 h, 32 = br*16+bb), 256 thr.
// dyn smem 102400: QS[2][64][136] @0, KS[2][64][136] @34816, Ls[2][64][64] @69632
// ---------------------------------------------------------------------------
__global__ __launch_bounds__(256) void k_attn1() {
    extern __shared__ char sm[];
    bft (*QS)[64][136] = reinterpret_cast<bft (*)[64][136]>(sm);
    bft (*KS)[64][136] = reinterpret_cast<bft (*)[64][136]>(sm + 34816);
    float (*Ls)[64][64] = reinterpret_cast<float (*)[64][64]>(sm + 69632);

    const int ns = blockIdx.x, h = blockIdx.y, z = blockIdx.z;
    const int br = z >> 4, bb = z & 15;
    const bft* __restrict__ Q  = &g_qkv[br * 3 + 0][bb][h * 64][0] + ns * 1024;
    const bft* __restrict__ Kk = &g_qkv[br * 3 + 1][bb][h * 64][0] + ns * 1024;
    const int tid = threadIdx.x, wid = tid >> 5;
    const int wm = (wid & 3) * 16, kh = wid >> 2;

    wmma::fragment<wmma::accumulator, 16, 16, 16, float> acc[4];
#pragma unroll
    for (int j = 0; j < 4; j++) wmma::fill_fragment(acc[j], 0.0f);

    auto pre = [&](int c, int buf) {
#pragma unroll
        for (int p = 0; p < 4; p++) {
            int idx = tid + p * 256;
            int r = idx >> 4, cl = (idx & 15) * 8;
            cp16(&QS[buf][r][cl], Q + (size_t)r * 4096 + c * 128 + cl);
            cp16(&KS[buf][r][cl], Kk + (size_t)r * 4096 + c * 128 + cl);
        }
        cpcommit();
    };
    pre(0, 0);
    for (int c = 0; c < 8; ++c) {
        const int buf = c & 1;
        cpwait<0>();
        __syncthreads();
        if (c < 7) pre(c + 1, buf ^ 1);
#pragma unroll
        for (int ks = 0; ks < 4; ks++) {
            wmma::fragment<wmma::matrix_a, 16, 16, 16, bft, wmma::row_major> af;
            wmma::load_matrix_sync(af, &QS[buf][wm][kh * 64 + ks * 16], 136);
#pragma unroll
            for (int j = 0; j < 4; j++) {
                wmma::fragment<wmma::matrix_b, 16, 16, 16, bft, wmma::col_major> bfr;
                wmma::load_matrix_sync(bfr, &KS[buf][j * 16][kh * 64 + ks * 16], 136);
                wmma::mma_sync(acc[j], af, bfr, acc[j]);
            }
        }
    }
#pragma unroll
    for (int j = 0; j < 4; j++)
        wmma::store_matrix_sync(&Ls[kh][wm][j * 16], acc[j], 64, wmma::mem_row_major);
    __syncthreads();

    // partial write: 256 threads x 16 floats
    {
        const int r = tid >> 2, c0 = (tid & 3) * 16;
        float* dst = &g_part[br][bb][h][ns][r][c0];
#pragma unroll
        for (int j = 0; j < 4; j++) {
            float4 a = *reinterpret_cast<const float4*>(&Ls[0][r][c0 + j * 4]);
            float4 b = *reinterpret_cast<const float4*>(&Ls[1][r][c0 + j * 4]);
            a.x += b.x; a.y += b.y; a.z += b.z; a.w += b.w;
            reinterpret_cast<float4*>(dst)[j] = a;
        }
    }
}

// ---------------------------------------------------------------------------
// K3b: reduce partials + softmax -> bf16 probs. grid=(8 h, 32 z), 64 thr.
// ---------------------------------------------------------------------------
__global__ __launch_bounds__(64) void k_softmax() {
    const int h = blockIdx.x, z = blockIdx.y;
    const int br = z >> 4, bb = z & 15;
    const int r = threadIdx.x;
    const float* p0 = &g_part[br][bb][h][0][r][0];
    float v[64];
#pragma unroll
    for (int j = 0; j < 16; j++) {
        float4 a = reinterpret_cast<const float4*>(p0)[j];
#pragma unroll
        for (int s = 1; s < 4; s++) {
            float4 b = reinterpret_cast<const float4*>(p0 + s * 4096)[j];
            a.x += b.x; a.y += b.y; a.z += b.z; a.w += b.w;
        }
        v[j * 4 + 0] = a.x; v[j * 4 + 1] = a.y; v[j * 4 + 2] = a.z; v[j * 4 + 3] = a.w;
    }
    const float scale = 0.125f;
    float mx = -1e30f;
#pragma unroll
    for (int j = 0; j < 64; j++) { v[j] *= scale; mx = fmaxf(mx, v[j]); }
    float s = 0.f;
#pragma unroll
    for (int j = 0; j < 64; j++) { v[j] = __expf(v[j] - mx); s += v[j]; }
    float inv = 1.0f / s;
    uint4 o[8];  // 64 bf16 = 128 bytes
    __nv_bfloat162* ph = reinterpret_cast<__nv_bfloat162*>(o);
#pragma unroll
    for (int j = 0; j < 32; j++) ph[j] = __floats2bfloat162_rn(v[2 * j] * inv, v[2 * j + 1] * inv);
    uint4* dst = reinterpret_cast<uint4*>(&g_probs[br][bb][h][r][0]);
#pragma unroll
    for (int j = 0; j < 8; j++) dst[j] = o[j];
}

// ---------------------------------------------------------------------------
// K3c: OutT[64, chunk] = probs^T @ V[64, chunk], chunk = 512 cols.
// grid=(8 nc, 8 h, 32 z), 256 thr.
// dyn smem 76800: VS[2][64][136] @0, Ps[64][72] @34816, OSw @44032 (32KB)
// ---------------------------------------------------------------------------
__global__ __launch_bounds__(256) void k_attn2() {
    extern __shared__ char sm[];
    bft (*VS)[64][136] = reinterpret_cast<bft (*)[64][136]>(sm);
    bft (*Ps)[72] = reinterpret_cast<bft (*)[72]>(sm + 34816);

    const int nc = blockIdx.x, h = blockIdx.y, z = blockIdx.z;
    const int br = z >> 4, bb = z & 15;
    const bft* __restrict__ V = &g_qkv[br * 3 + 2][bb][h * 64][0] + nc * 512;
    bft* __restrict__ O = &g_outb[br][bb][h * 64][0] + nc * 512;
    const bft* __restrict__ gp = &g_probs[br][bb][h][0][0];
    const int tid = threadIdx.x, wid = tid >> 5, lane = tid & 31;
    const int we = (wid & 3), wn = (wid >> 2) * 64;

    // load probs into padded smem
#pragma unroll
    for (int p = 0; p < 2; p++) {
        int idx = tid + p * 256;
        int r = idx >> 3, c = (idx & 7) * 8;
        *reinterpret_cast<uint4*>(&Ps[r][c]) =
            *reinterpret_cast<const uint4*>(gp + r * 64 + c);
    }

    auto pre = [&](int c, int buf) {
#pragma unroll
        for (int p = 0; p < 4; p++) {
            int idx = tid + p * 256;
            int r = idx >> 4, cl = (idx & 15) * 8;
            cp16(&VS[buf][r][cl], V + (size_t)r * 4096 + c * 128 + cl);
        }
        cpcommit();
    };
    pre(0, 0);
    __syncthreads();

    wmma::fragment<wmma::matrix_a, 16, 16, 16, bft, wmma::col_major> af[4];
#pragma unroll
    for (int d = 0; d < 4; d++)
        wmma::load_matrix_sync(af[d], &Ps[d * 16][we * 16], 72);

    float* OSw = reinterpret_cast<float*>(sm + 44032) + wid * 1024;  // 16x64 per warp
    for (int c = 0; c < 4; ++c) {
        const int buf = c & 1;
        cpwait<0>();
        __syncthreads();
        if (c < 3) pre(c + 1, buf ^ 1);
#pragma unroll
        for (int n4 = 0; n4 < 4; n4++) {
            wmma::fragment<wmma::accumulator, 16, 16, 16, float> oa;
            wmma::fill_fragment(oa, 0.0f);
#pragma unroll
            for (int d = 0; d < 4; d++) {
                wmma::fragment<wmma::matrix_b, 16, 16, 16, bft, wmma::row_major> bfr;
                wmma::load_matrix_sync(bfr, &VS[buf][d * 16][wn + n4 * 16], 136);
                wmma::mma_sync(oa, af[d], bfr, oa);
            }
            wmma::store_matrix_sync(OSw + n4 * 16, oa, 64, wmma::mem_row_major);
        }
        __syncwarp();
        {
            const int r = lane >> 1, c0 = (lane & 1) * 32;
            const float* src = OSw + r * 64 + c0;
            bft* dst = O + (size_t)(we * 16 + r) * 4096 + c * 128 + wn + c0;
            uint4 o[4];
            __nv_bfloat162* ph = reinterpret_cast<__nv_bfloat162*>(o);
#pragma unroll
            for (int q = 0; q < 16; q++)
                ph[q] = __floats2bfloat162_rn(src[2 * q], src[2 * q + 1]);
#pragma unroll
            for (int q = 0; q < 4; q++) reinterpret_cast<uint4*>(dst)[q] = o[q];
        }
        __syncwarp();
    }
}

// ---------------------------------------------------------------------------
// Launch. Input order: 0 rgb_emb, 1 geo_emb, 2 wq_rgb, 3 wk_rgb, 4 wv_rgb,
// 5 wq_point, 6 wk_point, 7 wv_point, 8 proj_r2p, 9 proj_p2r.
// ---------------------------------------------------------------------------
extern "C" void kernel_launch(void* const* d_in, const int* in_sizes, int n_in,
                              void* d_out, int out_size) {
    const float* rgb = (const float*)d_in[0];
    const float* geo = (const float*)d_in[1];

    cudaFuncSetAttribute(k_gemm_qkv, cudaFuncAttributeMaxDynamicSharedMemorySize, 156672);
    cudaFuncSetAttribute(k_gemm_final, cudaFuncAttributeMaxDynamicSharedMemorySize, 156672);
    cudaFuncSetAttribute(k_attn1, cudaFuncAttributeMaxDynamicSharedMemorySize, 102400);
    cudaFuncSetAttribute(k_attn2, cudaFuncAttributeMaxDynamicSharedMemorySize, 76800);

    k_convert<<<32768, 256>>>(rgb, geo);
    // weight slot order: 0 wq_rgb, 1 wk_point, 2 wv_point, 3 wq_point, 4 wk_rgb,
    //                    5 wv_rgb, 6 proj_p2r, 7 proj_r2p
    k_convw<<<dim3(256, 8), 256>>>((const float*)d_in[2], (const float*)d_in[6],
                                   (const float*)d_in[7], (const float*)d_in[5],
                                   (const float*)d_in[3], (const float*)d_in[4],
                                   (const float*)d_in[9], (const float*)d_in[8]);

    // dummy 3rd launch so the QKV GEMM is the 4th (profiled) launch
    k_dummy<<<1, 32>>>();

    // QKV projections: z = bb*6 + combo (batch-major for L2 reuse)
    k_gemm_qkv<<<dim3(16, 4, 96), 256, 156672>>>();

    // attention: partial logits -> softmax -> probs^T @ V
    k_attn1<<<dim3(4, 8, 32), 256, 102400>>>();
    k_softmax<<<dim3(8, 32), 64>>>();
    k_attn2<<<dim3(8, 8, 32), 256, 76800>>>();

    // fused output projections + residual -> d_out
    k_gemm_final<<<dim3(16, 4, 16), 256, 156672>>>(rgb, geo, (float*)d_out);
}